// round 10
// baseline (speedup 1.0000x reference)
#include <cuda_runtime.h>

#define BATCH 8
#define CHN   128
#define HWN   4096            // 64*64 pixels
#define CN    (CHN*HWN)       // 524288 per batch per tensor
#define GRP   8
#define CPG   (CHN/GRP)       // 16

// Scratch (allocation-free: __device__ globals)
__device__ float g_H[BATCH*CN];        // groupnorm output
__device__ float g_QKV[BATCH*3*CN];    // qkv conv output
__device__ float g_O[BATCH*CN];        // attention output

// ---------------------------------------------------------------------------
// GroupNorm: one CTA per (batch, group). Group data is a contiguous 65536-float
// block (channels are contiguous in memory).
// ---------------------------------------------------------------------------
__global__ void gn_kernel(const float* __restrict__ x,
                          const float* __restrict__ w,
                          const float* __restrict__ bb,
                          float* __restrict__ H)
{
    int b = blockIdx.x / GRP;
    int g = blockIdx.x % GRP;
    const float* xp = x + (long)b*CN + (long)g*CPG*HWN;
    float*       hp = H + (long)b*CN + (long)g*CPG*HWN;
    const int NE = CPG*HWN;   // 65536

    float s = 0.f, ss = 0.f;
    for (int i = threadIdx.x*4; i < NE; i += blockDim.x*4) {
        float4 v = *(const float4*)(xp + i);
        s  += v.x + v.y + v.z + v.w;
        ss += v.x*v.x + v.y*v.y + v.z*v.z + v.w*v.w;
    }
    __shared__ float rs[256], rss[256];
    rs[threadIdx.x] = s; rss[threadIdx.x] = ss;
    __syncthreads();
    for (int off = 128; off > 0; off >>= 1) {
        if (threadIdx.x < off) {
            rs[threadIdx.x]  += rs[threadIdx.x + off];
            rss[threadIdx.x] += rss[threadIdx.x + off];
        }
        __syncthreads();
    }
    float mean = rs[0] / (float)NE;
    float var  = rss[0] / (float)NE - mean*mean;
    float inv  = rsqrtf(var + 1e-5f);

    for (int i = threadIdx.x*4; i < NE; i += blockDim.x*4) {
        int c = g*CPG + (i >> 12);       // i/4096; float4 never crosses channel
        float wc = w[c], bc = bb[c];
        float4 v = *(const float4*)(xp + i);
        v.x = (v.x - mean)*inv*wc + bc;
        v.y = (v.y - mean)*inv*wc + bc;
        v.z = (v.z - mean)*inv*wc + bc;
        v.w = (v.w - mean)*inv*wc + bc;
        *(float4*)(hp + i) = v;
    }
}

// ---------------------------------------------------------------------------
// 1x1 conv == per-batch GEMM: out[o,n] = sum_c W[o,c]*inp[c,n] + bias[o]
// Tile: 64 o x 64 n, K=128 fully resident in smem. 256 thr, 4x4 microtile.
// Optional residual add (for the proj + x epilogue).
// ---------------------------------------------------------------------------
__global__ void conv1x1_kernel(const float* __restrict__ inp,
                               const float* __restrict__ Wt,
                               const float* __restrict__ bias,
                               float* __restrict__ out, long ob_stride,
                               const float* __restrict__ resid)
{
    extern __shared__ float sm[];
    float* ws = sm;              // [64][128]
    float* hs = sm + 64*128;     // [128][64]

    int b  = blockIdx.z;
    int nb = blockIdx.x * 64;
    int ob = blockIdx.y * 64;
    int tid = threadIdx.x;
    const float* inb = inp + (long)b*CN;

    for (int idx = tid; idx < 8192; idx += 256) {
        int o = idx >> 7, c = idx & 127;
        ws[idx] = Wt[(long)(ob + o)*CHN + c];
    }
    for (int idx = tid; idx < 8192; idx += 256) {
        int c = idx >> 6, nn = idx & 63;
        hs[idx] = inb[(long)c*HWN + nb + nn];
    }
    __syncthreads();

    int ti = tid >> 4, tj = tid & 15;
    float acc[4][4] = {};
    const float* hp = hs + tj*4;
    const float* wp = ws + (ti*4)*CHN;

    #pragma unroll 4
    for (int c = 0; c < CHN; ++c) {
        float4 h4 = *(const float4*)(hp + c*64);
        float w0 = wp[0*CHN + c];
        float w1 = wp[1*CHN + c];
        float w2 = wp[2*CHN + c];
        float w3 = wp[3*CHN + c];
        acc[0][0] += w0*h4.x; acc[0][1] += w0*h4.y; acc[0][2] += w0*h4.z; acc[0][3] += w0*h4.w;
        acc[1][0] += w1*h4.x; acc[1][1] += w1*h4.y; acc[1][2] += w1*h4.z; acc[1][3] += w1*h4.w;
        acc[2][0] += w2*h4.x; acc[2][1] += w2*h4.y; acc[2][2] += w2*h4.z; acc[2][3] += w2*h4.w;
        acc[3][0] += w3*h4.x; acc[3][1] += w3*h4.y; acc[3][2] += w3*h4.z; acc[3][3] += w3*h4.w;
    }

    #pragma unroll
    for (int r = 0; r < 4; ++r) {
        int o = ob + ti*4 + r;
        float bo = bias[o];
        float4 v;
        v.x = acc[r][0] + bo; v.y = acc[r][1] + bo;
        v.z = acc[r][2] + bo; v.w = acc[r][3] + bo;
        long off = (long)o*HWN + nb + tj*4;
        if (resid) {
            float4 rr = *(const float4*)(resid + (long)b*CN + off);
            v.x += rr.x; v.y += rr.y; v.z += rr.z; v.w += rr.w;
        }
        *(float4*)(out + (long)b*ob_stride + off) = v;
    }
}

// ---------------------------------------------------------------------------
// Flash attention: one CTA per (64-query tile, batch). 256 threads.
//   S[i,j] = sum_c qs[c,i]*ks[c,j]  (q pre-scaled by C^-0.5)
//   online softmax over j tiles of 64; O[i,c] += P[i,j]*V[c,j]
// V staged transposed (vst[j][c], row stride 132 floats -> 16B aligned,
// conflict-free float4 reads in the PV loop).
// ---------------------------------------------------------------------------
#define VSTRIDE 132

__global__ void attn_kernel(const float* __restrict__ qkv, float* __restrict__ og)
{
    extern __shared__ float sm[];
    float* qs   = sm;                  // 128*64 = 8192
    float* ks   = sm + 8192;           // 8192
    float* vst  = sm + 16384;          // 64*132 = 8448
    float* st   = vst + 64*VSTRIDE;    // 64*64  = 4096
    float* s_m  = st + 4096;           // 64
    float* s_l  = s_m + 64;            // 64
    float* s_mn = s_l + 64;            // 64
    float* s_co = s_mn + 64;           // 64

    int b  = blockIdx.y;
    int i0 = blockIdx.x * 64;
    const float* q = qkv + (long)b*3*CN;
    const float* k = q + CN;
    const float* v = q + 2*CN;
    int tid = threadIdx.x;
    int ti = tid >> 4, tj = tid & 15;
    const float scale = 0.08838834764831845f;  // 128^-0.5

    for (int idx = tid; idx < 8192; idx += 256) {
        int c = idx >> 6, ii = idx & 63;
        qs[idx] = q[(long)c*HWN + i0 + ii] * scale;
    }
    if (tid < 64) { s_m[tid] = -1e30f; s_l[tid] = 0.f; }
    float acc[4][8] = {};
    __syncthreads();

    for (int jt = 0; jt < 64; ++jt) {
        int j0 = jt * 64;
        // load K tile [c][j] and V tile transposed [j][c]
        for (int idx = tid; idx < 8192; idx += 256) {
            int c = idx >> 6, jj = idx & 63;
            ks[idx] = k[(long)c*HWN + j0 + jj];
            vst[jj*VSTRIDE + c] = v[(long)c*HWN + j0 + jj];
        }
        __syncthreads();

        // ---- S = Q^T K (4x4 microtile per thread) ----
        float s[4][4] = {};
        const float* qp = qs + ti*4;
        const float* kp = ks + tj*4;
        #pragma unroll 4
        for (int c = 0; c < CHN; ++c) {
            float4 q4 = *(const float4*)(qp + c*64);
            float4 k4 = *(const float4*)(kp + c*64);
            s[0][0] += q4.x*k4.x; s[0][1] += q4.x*k4.y; s[0][2] += q4.x*k4.z; s[0][3] += q4.x*k4.w;
            s[1][0] += q4.y*k4.x; s[1][1] += q4.y*k4.y; s[1][2] += q4.y*k4.z; s[1][3] += q4.y*k4.w;
            s[2][0] += q4.z*k4.x; s[2][1] += q4.z*k4.y; s[2][2] += q4.z*k4.z; s[2][3] += q4.z*k4.w;
            s[3][0] += q4.w*k4.x; s[3][1] += q4.w*k4.y; s[3][2] += q4.w*k4.z; s[3][3] += q4.w*k4.w;
        }
        #pragma unroll
        for (int r = 0; r < 4; ++r) {
            float4 sv = make_float4(s[r][0], s[r][1], s[r][2], s[r][3]);
            *(float4*)(st + (ti*4 + r)*64 + tj*4) = sv;
        }
        __syncthreads();

        // ---- row max + correction factors ----
        if (tid < 64) {
            float mo = s_m[tid];
            float mt = -1e30f;
            const float* row = st + tid*64;
            #pragma unroll 8
            for (int j = 0; j < 64; ++j) mt = fmaxf(mt, row[j]);
            float mn = fmaxf(mo, mt);
            s_mn[tid] = mn;
            s_co[tid] = __expf(mo - mn);
        }
        __syncthreads();

        // ---- P = exp(S - m_new) in place; rescale O accumulators ----
        #pragma unroll
        for (int r = 0; r < 4; ++r) {
            float mn = s_mn[ti*4 + r];
            float co = s_co[ti*4 + r];
            float4 pv;
            pv.x = __expf(s[r][0] - mn);
            pv.y = __expf(s[r][1] - mn);
            pv.z = __expf(s[r][2] - mn);
            pv.w = __expf(s[r][3] - mn);
            *(float4*)(st + (ti*4 + r)*64 + tj*4) = pv;
            #pragma unroll
            for (int cc = 0; cc < 8; ++cc) acc[r][cc] *= co;
        }
        __syncthreads();

        // ---- row sums update l,m (64 threads) + O += P V^T (all threads) ----
        if (tid < 64) {
            const float* row = st + tid*64;
            float sum = 0.f;
            #pragma unroll 8
            for (int j = 0; j < 64; ++j) sum += row[j];
            s_l[tid] = s_l[tid]*s_co[tid] + sum;
            s_m[tid] = s_mn[tid];
        }
        const float* vp = vst + tj*8;
        const float* sp = st + ti*4*64;
        #pragma unroll 2
        for (int j = 0; j < 64; ++j) {
            float p0 = sp[0*64 + j];
            float p1 = sp[1*64 + j];
            float p2 = sp[2*64 + j];
            float p3 = sp[3*64 + j];
            float4 va = *(const float4*)(vp + j*VSTRIDE);
            float4 vb = *(const float4*)(vp + j*VSTRIDE + 4);
            acc[0][0] += p0*va.x; acc[0][1] += p0*va.y; acc[0][2] += p0*va.z; acc[0][3] += p0*va.w;
            acc[0][4] += p0*vb.x; acc[0][5] += p0*vb.y; acc[0][6] += p0*vb.z; acc[0][7] += p0*vb.w;
            acc[1][0] += p1*va.x; acc[1][1] += p1*va.y; acc[1][2] += p1*va.z; acc[1][3] += p1*va.w;
            acc[1][4] += p1*vb.x; acc[1][5] += p1*vb.y; acc[1][6] += p1*vb.z; acc[1][7] += p1*vb.w;
            acc[2][0] += p2*va.x; acc[2][1] += p2*va.y; acc[2][2] += p2*va.z; acc[2][3] += p2*va.w;
            acc[2][4] += p2*vb.x; acc[2][5] += p2*vb.y; acc[2][6] += p2*vb.z; acc[2][7] += p2*vb.w;
            acc[3][0] += p3*va.x; acc[3][1] += p3*va.y; acc[3][2] += p3*va.z; acc[3][3] += p3*va.w;
            acc[3][4] += p3*vb.x; acc[3][5] += p3*vb.y; acc[3][6] += p3*vb.z; acc[3][7] += p3*vb.w;
        }
        __syncthreads();
    }

    // ---- epilogue: O / l, stage to [c][ii] layout for coalesced store ----
    float linv[4];
    #pragma unroll
    for (int r = 0; r < 4; ++r) linv[r] = 1.0f / s_l[ti*4 + r];
    #pragma unroll
    for (int r = 0; r < 4; ++r)
        #pragma unroll
        for (int cc = 0; cc < 8; ++cc)
            qs[(tj*8 + cc)*64 + ti*4 + r] = acc[r][cc] * linv[r];
    __syncthreads();

    float* ob = og + (long)b*CN;
    for (int idx = tid; idx < 8192; idx += 256) {
        int c = idx >> 6, ii = idx & 63;
        ob[(long)c*HWN + i0 + ii] = qs[idx];
    }
}

// ---------------------------------------------------------------------------
extern "C" void kernel_launch(void* const* d_in, const int* in_sizes, int n_in,
                              void* d_out, int out_size)
{
    const float* x      = (const float*)d_in[0];
    const float* gn_w   = (const float*)d_in[1];
    const float* gn_b   = (const float*)d_in[2];
    const float* qkv_w  = (const float*)d_in[3];
    const float* qkv_b  = (const float*)d_in[4];
    const float* proj_w = (const float*)d_in[5];
    const float* proj_b = (const float*)d_in[6];
    float* out = (float*)d_out;

    float *H, *QKV, *O;
    cudaGetSymbolAddress((void**)&H,   g_H);
    cudaGetSymbolAddress((void**)&QKV, g_QKV);
    cudaGetSymbolAddress((void**)&O,   g_O);

    const int CONV_SMEM = 2 * 8192 * 4;                               // 64 KB
    const int ATTN_SMEM = (8192 + 8192 + 64*VSTRIDE + 4096 + 256)*4;  // ~114 KB
    cudaFuncSetAttribute(conv1x1_kernel, cudaFuncAttributeMaxDynamicSharedMemorySize, CONV_SMEM);
    cudaFuncSetAttribute(attn_kernel,    cudaFuncAttributeMaxDynamicSharedMemorySize, ATTN_SMEM);

    // 1) GroupNorm
    gn_kernel<<<BATCH*GRP, 256>>>(x, gn_w, gn_b, H);
    // 2) QKV 1x1 conv: [384,128] @ [128,4096] per batch
    conv1x1_kernel<<<dim3(64, 6, BATCH), 256, CONV_SMEM>>>(H, qkv_w, qkv_b, QKV, 3L*CN, nullptr);
    // 3) Flash attention
    attn_kernel<<<dim3(64, BATCH), 256, ATTN_SMEM>>>(QKV, O);
    // 4) proj 1x1 conv + residual -> d_out
    conv1x1_kernel<<<dim3(64, 2, BATCH), 256, CONV_SMEM>>>(O, proj_w, proj_b, out, (long)CN, x);
}

// round 11
// speedup vs baseline: 1.0119x; 1.0119x over previous
#include <cuda_runtime.h>

#define BATCH 8
#define CHN   128
#define HWN   4096            // 64*64 pixels
#define CN    (CHN*HWN)       // 524288 per batch per tensor
#define GRP   8
#define CPG   (CHN/GRP)       // 16

// Scratch (allocation-free: __device__ globals)
__device__ float g_H[BATCH*CN];        // groupnorm output
__device__ float g_QKV[BATCH*3*CN];    // qkv conv output
__device__ float g_O[BATCH*CN];        // attention output

// ---------------------------------------------------------------------------
// GroupNorm: one CTA per (batch, group). Group data is a contiguous 65536-float
// block (channels are contiguous in memory).
// ---------------------------------------------------------------------------
__global__ void gn_kernel(const float* __restrict__ x,
                          const float* __restrict__ w,
                          const float* __restrict__ bb,
                          float* __restrict__ H)
{
    int b = blockIdx.x / GRP;
    int g = blockIdx.x % GRP;
    const float* xp = x + (long)b*CN + (long)g*CPG*HWN;
    float*       hp = H + (long)b*CN + (long)g*CPG*HWN;
    const int NE = CPG*HWN;   // 65536

    float s = 0.f, ss = 0.f;
    for (int i = threadIdx.x*4; i < NE; i += blockDim.x*4) {
        float4 v = *(const float4*)(xp + i);
        s  += v.x + v.y + v.z + v.w;
        ss += v.x*v.x + v.y*v.y + v.z*v.z + v.w*v.w;
    }
    __shared__ float rs[256], rss[256];
    rs[threadIdx.x] = s; rss[threadIdx.x] = ss;
    __syncthreads();
    for (int off = 128; off > 0; off >>= 1) {
        if (threadIdx.x < off) {
            rs[threadIdx.x]  += rs[threadIdx.x + off];
            rss[threadIdx.x] += rss[threadIdx.x + off];
        }
        __syncthreads();
    }
    float mean = rs[0] / (float)NE;
    float var  = rss[0] / (float)NE - mean*mean;
    float inv  = rsqrtf(var + 1e-5f);

    for (int i = threadIdx.x*4; i < NE; i += blockDim.x*4) {
        int c = g*CPG + (i >> 12);       // i/4096; float4 never crosses channel
        float wc = w[c], bc = bb[c];
        float4 v = *(const float4*)(xp + i);
        v.x = (v.x - mean)*inv*wc + bc;
        v.y = (v.y - mean)*inv*wc + bc;
        v.z = (v.z - mean)*inv*wc + bc;
        v.w = (v.w - mean)*inv*wc + bc;
        *(float4*)(hp + i) = v;
    }
}

// ---------------------------------------------------------------------------
// 1x1 conv == per-batch GEMM: out[o,n] = sum_c W[o,c]*inp[c,n] + bias[o]
// Tile: 64 o x 64 n, K=128 fully resident in smem. 256 thr, 4x4 microtile.
// Optional residual add (for the proj + x epilogue).
// ---------------------------------------------------------------------------
__global__ void conv1x1_kernel(const float* __restrict__ inp,
                               const float* __restrict__ Wt,
                               const float* __restrict__ bias,
                               float* __restrict__ out, long ob_stride,
                               const float* __restrict__ resid)
{
    extern __shared__ float sm[];
    float* ws = sm;              // [64][128]
    float* hs = sm + 64*128;     // [128][64]

    int b  = blockIdx.z;
    int nb = blockIdx.x * 64;
    int ob = blockIdx.y * 64;
    int tid = threadIdx.x;
    const float* inb = inp + (long)b*CN;

    for (int idx = tid; idx < 8192; idx += 256) {
        int o = idx >> 7, c = idx & 127;
        ws[idx] = Wt[(long)(ob + o)*CHN + c];
    }
    for (int idx = tid; idx < 8192; idx += 256) {
        int c = idx >> 6, nn = idx & 63;
        hs[idx] = inb[(long)c*HWN + nb + nn];
    }
    __syncthreads();

    int ti = tid >> 4, tj = tid & 15;
    float acc[4][4] = {};
    const float* hp = hs + tj*4;
    const float* wp = ws + (ti*4)*CHN;

    #pragma unroll 4
    for (int c = 0; c < CHN; ++c) {
        float4 h4 = *(const float4*)(hp + c*64);
        float w0 = wp[0*CHN + c];
        float w1 = wp[1*CHN + c];
        float w2 = wp[2*CHN + c];
        float w3 = wp[3*CHN + c];
        acc[0][0] += w0*h4.x; acc[0][1] += w0*h4.y; acc[0][2] += w0*h4.z; acc[0][3] += w0*h4.w;
        acc[1][0] += w1*h4.x; acc[1][1] += w1*h4.y; acc[1][2] += w1*h4.z; acc[1][3] += w1*h4.w;
        acc[2][0] += w2*h4.x; acc[2][1] += w2*h4.y; acc[2][2] += w2*h4.z; acc[2][3] += w2*h4.w;
        acc[3][0] += w3*h4.x; acc[3][1] += w3*h4.y; acc[3][2] += w3*h4.z; acc[3][3] += w3*h4.w;
    }

    #pragma unroll
    for (int r = 0; r < 4; ++r) {
        int o = ob + ti*4 + r;
        float bo = bias[o];
        float4 v;
        v.x = acc[r][0] + bo; v.y = acc[r][1] + bo;
        v.z = acc[r][2] + bo; v.w = acc[r][3] + bo;
        long off = (long)o*HWN + nb + tj*4;
        if (resid) {
            float4 rr = *(const float4*)(resid + (long)b*CN + off);
            v.x += rr.x; v.y += rr.y; v.z += rr.z; v.w += rr.w;
        }
        *(float4*)(out + (long)b*ob_stride + off) = v;
    }
}

// ---------------------------------------------------------------------------
// Flash attention: one CTA per (64-query tile, batch). 256 threads.
//   S[i,j] = sum_c qs[c,i]*ks[c,j]  (q pre-scaled by C^-0.5)
//   online softmax over j tiles of 64; O[i,c] += P[i,j]*V[c,j]
// V staged transposed (vst[j][c], row stride 132 floats -> 16B aligned,
// conflict-free float4 reads in the PV loop).
// ---------------------------------------------------------------------------
#define VSTRIDE 132

__global__ void attn_kernel(const float* __restrict__ qkv, float* __restrict__ og)
{
    extern __shared__ float sm[];
    float* qs   = sm;                  // 128*64 = 8192
    float* ks   = sm + 8192;           // 8192
    float* vst  = sm + 16384;          // 64*132 = 8448
    float* st   = vst + 64*VSTRIDE;    // 64*64  = 4096
    float* s_m  = st + 4096;           // 64
    float* s_l  = s_m + 64;            // 64
    float* s_mn = s_l + 64;            // 64
    float* s_co = s_mn + 64;           // 64

    int b  = blockIdx.y;
    int i0 = blockIdx.x * 64;
    const float* q = qkv + (long)b*3*CN;
    const float* k = q + CN;
    const float* v = q + 2*CN;
    int tid = threadIdx.x;
    int ti = tid >> 4, tj = tid & 15;
    const float scale = 0.08838834764831845f;  // 128^-0.5

    for (int idx = tid; idx < 8192; idx += 256) {
        int c = idx >> 6, ii = idx & 63;
        qs[idx] = q[(long)c*HWN + i0 + ii] * scale;
    }
    if (tid < 64) { s_m[tid] = -1e30f; s_l[tid] = 0.f; }
    float acc[4][8] = {};
    __syncthreads();

    for (int jt = 0; jt < 64; ++jt) {
        int j0 = jt * 64;
        // load K tile [c][j] and V tile transposed [j][c]
        for (int idx = tid; idx < 8192; idx += 256) {
            int c = idx >> 6, jj = idx & 63;
            ks[idx] = k[(long)c*HWN + j0 + jj];
            vst[jj*VSTRIDE + c] = v[(long)c*HWN + j0 + jj];
        }
        __syncthreads();

        // ---- S = Q^T K (4x4 microtile per thread) ----
        float s[4][4] = {};
        const float* qp = qs + ti*4;
        const float* kp = ks + tj*4;
        #pragma unroll 4
        for (int c = 0; c < CHN; ++c) {
            float4 q4 = *(const float4*)(qp + c*64);
            float4 k4 = *(const float4*)(kp + c*64);
            s[0][0] += q4.x*k4.x; s[0][1] += q4.x*k4.y; s[0][2] += q4.x*k4.z; s[0][3] += q4.x*k4.w;
            s[1][0] += q4.y*k4.x; s[1][1] += q4.y*k4.y; s[1][2] += q4.y*k4.z; s[1][3] += q4.y*k4.w;
            s[2][0] += q4.z*k4.x; s[2][1] += q4.z*k4.y; s[2][2] += q4.z*k4.z; s[2][3] += q4.z*k4.w;
            s[3][0] += q4.w*k4.x; s[3][1] += q4.w*k4.y; s[3][2] += q4.w*k4.z; s[3][3] += q4.w*k4.w;
        }
        #pragma unroll
        for (int r = 0; r < 4; ++r) {
            float4 sv = make_float4(s[r][0], s[r][1], s[r][2], s[r][3]);
            *(float4*)(st + (ti*4 + r)*64 + tj*4) = sv;
        }
        __syncthreads();

        // ---- row max + correction factors ----
        if (tid < 64) {
            float mo = s_m[tid];
            float mt = -1e30f;
            const float* row = st + tid*64;
            #pragma unroll 8
            for (int j = 0; j < 64; ++j) mt = fmaxf(mt, row[j]);
            float mn = fmaxf(mo, mt);
            s_mn[tid] = mn;
            s_co[tid] = __expf(mo - mn);
        }
        __syncthreads();

        // ---- P = exp(S - m_new) in place; rescale O accumulators ----
        #pragma unroll
        for (int r = 0; r < 4; ++r) {
            float mn = s_mn[ti*4 + r];
            float co = s_co[ti*4 + r];
            float4 pv;
            pv.x = __expf(s[r][0] - mn);
            pv.y = __expf(s[r][1] - mn);
            pv.z = __expf(s[r][2] - mn);
            pv.w = __expf(s[r][3] - mn);
            *(float4*)(st + (ti*4 + r)*64 + tj*4) = pv;
            #pragma unroll
            for (int cc = 0; cc < 8; ++cc) acc[r][cc] *= co;
        }
        __syncthreads();

        // ---- row sums update l,m (64 threads) + O += P V^T (all threads) ----
        if (tid < 64) {
            const float* row = st + tid*64;
            float sum = 0.f;
            #pragma unroll 8
            for (int j = 0; j < 64; ++j) sum += row[j];
            s_l[tid] = s_l[tid]*s_co[tid] + sum;
            s_m[tid] = s_mn[tid];
        }
        const float* vp = vst + tj*8;
        const float* sp = st + ti*4*64;
        #pragma unroll 2
        for (int j = 0; j < 64; ++j) {
            float p0 = sp[0*64 + j];
            float p1 = sp[1*64 + j];
            float p2 = sp[2*64 + j];
            float p3 = sp[3*64 + j];
            float4 va = *(const float4*)(vp + j*VSTRIDE);
            float4 vb = *(const float4*)(vp + j*VSTRIDE + 4);
            acc[0][0] += p0*va.x; acc[0][1] += p0*va.y; acc[0][2] += p0*va.z; acc[0][3] += p0*va.w;
            acc[0][4] += p0*vb.x; acc[0][5] += p0*vb.y; acc[0][6] += p0*vb.z; acc[0][7] += p0*vb.w;
            acc[1][0] += p1*va.x; acc[1][1] += p1*va.y; acc[1][2] += p1*va.z; acc[1][3] += p1*va.w;
            acc[1][4] += p1*vb.x; acc[1][5] += p1*vb.y; acc[1][6] += p1*vb.z; acc[1][7] += p1*vb.w;
            acc[2][0] += p2*va.x; acc[2][1] += p2*va.y; acc[2][2] += p2*va.z; acc[2][3] += p2*va.w;
            acc[2][4] += p2*vb.x; acc[2][5] += p2*vb.y; acc[2][6] += p2*vb.z; acc[2][7] += p2*vb.w;
            acc[3][0] += p3*va.x; acc[3][1] += p3*va.y; acc[3][2] += p3*va.z; acc[3][3] += p3*va.w;
            acc[3][4] += p3*vb.x; acc[3][5] += p3*vb.y; acc[3][6] += p3*vb.z; acc[3][7] += p3*vb.w;
        }
        __syncthreads();
    }

    // ---- epilogue: O / l, stage to [c][ii] layout for coalesced store ----
    float linv[4];
    #pragma unroll
    for (int r = 0; r < 4; ++r) linv[r] = 1.0f / s_l[ti*4 + r];
    #pragma unroll
    for (int r = 0; r < 4; ++r)
        #pragma unroll
        for (int cc = 0; cc < 8; ++cc)
            qs[(tj*8 + cc)*64 + ti*4 + r] = acc[r][cc] * linv[r];
    __syncthreads();

    float* ob = og + (long)b*CN;
    for (int idx = tid; idx < 8192; idx += 256) {
        int c = idx >> 6, ii = idx & 63;
        ob[(long)c*HWN + i0 + ii] = qs[idx];
    }
}

// ---------------------------------------------------------------------------
extern "C" void kernel_launch(void* const* d_in, const int* in_sizes, int n_in,
                              void* d_out, int out_size)
{
    const float* x      = (const float*)d_in[0];
    const float* gn_w   = (const float*)d_in[1];
    const float* gn_b   = (const float*)d_in[2];
    const float* qkv_w  = (const float*)d_in[3];
    const float* qkv_b  = (const float*)d_in[4];
    const float* proj_w = (const float*)d_in[5];
    const float* proj_b = (const float*)d_in[6];
    float* out = (float*)d_out;

    float *H, *QKV, *O;
    cudaGetSymbolAddress((void**)&H,   g_H);
    cudaGetSymbolAddress((void**)&QKV, g_QKV);
    cudaGetSymbolAddress((void**)&O,   g_O);

    const int CONV_SMEM = 2 * 8192 * 4;                               // 64 KB
    const int ATTN_SMEM = (8192 + 8192 + 64*VSTRIDE + 4096 + 256)*4;  // ~114 KB
    cudaFuncSetAttribute(conv1x1_kernel, cudaFuncAttributeMaxDynamicSharedMemorySize, CONV_SMEM);
    cudaFuncSetAttribute(attn_kernel,    cudaFuncAttributeMaxDynamicSharedMemorySize, ATTN_SMEM);

    // 1) GroupNorm
    gn_kernel<<<BATCH*GRP, 256>>>(x, gn_w, gn_b, H);
    // 2) QKV 1x1 conv: [384,128] @ [128,4096] per batch
    conv1x1_kernel<<<dim3(64, 6, BATCH), 256, CONV_SMEM>>>(H, qkv_w, qkv_b, QKV, 3L*CN, nullptr);
    // 3) Flash attention
    attn_kernel<<<dim3(64, BATCH), 256, ATTN_SMEM>>>(QKV, O);
    // 4) proj 1x1 conv + residual -> d_out
    conv1x1_kernel<<<dim3(64, 2, BATCH), 256, CONV_SMEM>>>(O, proj_w, proj_b, out, (long)CN, x);
}

// round 12
// speedup vs baseline: 1.5372x; 1.5191x over previous
#include <cuda_runtime.h>

#define BATCH 8
#define CHN   128
#define HWN   4096            // 64*64 pixels
#define CN    (CHN*HWN)       // 524288 per batch per tensor
#define GRP   8
#define CPG   (CHN/GRP)       // 16

// Scratch (allocation-free: __device__ globals)
__device__ float g_H[BATCH*CN];        // groupnorm output
__device__ float g_QKV[BATCH*3*CN];    // qkv conv output
__device__ float g_O[BATCH*CN];        // attention output

// ---------------- packed f32x2 helpers (sm_100+ PTX) -----------------------
__device__ __forceinline__ unsigned long long pk2(float f) {
    unsigned long long d;
    asm("mov.b64 %0, {%1, %1};" : "=l"(d) : "f"(f));
    return d;
}
__device__ __forceinline__ unsigned long long ffma2(unsigned long long a,
                                                    unsigned long long b,
                                                    unsigned long long c) {
    unsigned long long d;
    asm("fma.rn.f32x2 %0, %1, %2, %3;" : "=l"(d) : "l"(a), "l"(b), "l"(c));
    return d;
}
__device__ __forceinline__ unsigned long long fmul2(unsigned long long a,
                                                    unsigned long long b) {
    unsigned long long d;
    asm("mul.rn.f32x2 %0, %1, %2;" : "=l"(d) : "l"(a), "l"(b));
    return d;
}
__device__ __forceinline__ void unpk2(unsigned long long d, float& a, float& b) {
    asm("mov.b64 {%0, %1}, %2;" : "=f"(a), "=f"(b) : "l"(d));
}

// ---------------------------------------------------------------------------
// GroupNorm: one CTA per (batch, group). Group data is a contiguous 65536-float
// block (channels are contiguous in memory).
// ---------------------------------------------------------------------------
__global__ void gn_kernel(const float* __restrict__ x,
                          const float* __restrict__ w,
                          const float* __restrict__ bb,
                          float* __restrict__ H)
{
    int b = blockIdx.x / GRP;
    int g = blockIdx.x % GRP;
    const float* xp = x + (long)b*CN + (long)g*CPG*HWN;
    float*       hp = H + (long)b*CN + (long)g*CPG*HWN;
    const int NE = CPG*HWN;   // 65536

    float s = 0.f, ss = 0.f;
    for (int i = threadIdx.x*4; i < NE; i += blockDim.x*4) {
        float4 v = *(const float4*)(xp + i);
        s  += v.x + v.y + v.z + v.w;
        ss += v.x*v.x + v.y*v.y + v.z*v.z + v.w*v.w;
    }
    __shared__ float rs[256], rss[256];
    rs[threadIdx.x] = s; rss[threadIdx.x] = ss;
    __syncthreads();
    for (int off = 128; off > 0; off >>= 1) {
        if (threadIdx.x < off) {
            rs[threadIdx.x]  += rs[threadIdx.x + off];
            rss[threadIdx.x] += rss[threadIdx.x + off];
        }
        __syncthreads();
    }
    float mean = rs[0] / (float)NE;
    float var  = rss[0] / (float)NE - mean*mean;
    float inv  = rsqrtf(var + 1e-5f);

    for (int i = threadIdx.x*4; i < NE; i += blockDim.x*4) {
        int c = g*CPG + (i >> 12);       // i/4096; float4 never crosses channel
        float wc = w[c], bc = bb[c];
        float4 v = *(const float4*)(xp + i);
        v.x = (v.x - mean)*inv*wc + bc;
        v.y = (v.y - mean)*inv*wc + bc;
        v.z = (v.z - mean)*inv*wc + bc;
        v.w = (v.w - mean)*inv*wc + bc;
        *(float4*)(hp + i) = v;
    }
}

// ---------------------------------------------------------------------------
// 1x1 conv == per-batch GEMM: out[o,n] = sum_c W[o,c]*inp[c,n] + bias[o]
// Tile: 64 o x 64 n, K=128 fully resident in smem. 256 thr, 4x4 microtile.
// Optional residual add (for the proj + x epilogue).
// ---------------------------------------------------------------------------
__global__ void conv1x1_kernel(const float* __restrict__ inp,
                               const float* __restrict__ Wt,
                               const float* __restrict__ bias,
                               float* __restrict__ out, long ob_stride,
                               const float* __restrict__ resid)
{
    extern __shared__ float sm[];
    float* ws = sm;              // [64][128]
    float* hs = sm + 64*128;     // [128][64]

    int b  = blockIdx.z;
    int nb = blockIdx.x * 64;
    int ob = blockIdx.y * 64;
    int tid = threadIdx.x;
    const float* inb = inp + (long)b*CN;

    for (int idx = tid; idx < 8192; idx += 256) {
        int o = idx >> 7, c = idx & 127;
        ws[idx] = Wt[(long)(ob + o)*CHN + c];
    }
    for (int idx = tid; idx < 8192; idx += 256) {
        int c = idx >> 6, nn = idx & 63;
        hs[idx] = inb[(long)c*HWN + nb + nn];
    }
    __syncthreads();

    int ti = tid >> 4, tj = tid & 15;
    float acc[4][4] = {};
    const float* hp = hs + tj*4;
    const float* wp = ws + (ti*4)*CHN;

    #pragma unroll 4
    for (int c = 0; c < CHN; ++c) {
        float4 h4 = *(const float4*)(hp + c*64);
        float w0 = wp[0*CHN + c];
        float w1 = wp[1*CHN + c];
        float w2 = wp[2*CHN + c];
        float w3 = wp[3*CHN + c];
        acc[0][0] += w0*h4.x; acc[0][1] += w0*h4.y; acc[0][2] += w0*h4.z; acc[0][3] += w0*h4.w;
        acc[1][0] += w1*h4.x; acc[1][1] += w1*h4.y; acc[1][2] += w1*h4.z; acc[1][3] += w1*h4.w;
        acc[2][0] += w2*h4.x; acc[2][1] += w2*h4.y; acc[2][2] += w2*h4.z; acc[2][3] += w2*h4.w;
        acc[3][0] += w3*h4.x; acc[3][1] += w3*h4.y; acc[3][2] += w3*h4.z; acc[3][3] += w3*h4.w;
    }

    #pragma unroll
    for (int r = 0; r < 4; ++r) {
        int o = ob + ti*4 + r;
        float bo = bias[o];
        float4 v;
        v.x = acc[r][0] + bo; v.y = acc[r][1] + bo;
        v.z = acc[r][2] + bo; v.w = acc[r][3] + bo;
        long off = (long)o*HWN + nb + tj*4;
        if (resid) {
            float4 rr = *(const float4*)(resid + (long)b*CN + off);
            v.x += rr.x; v.y += rr.y; v.z += rr.z; v.w += rr.w;
        }
        *(float4*)(out + (long)b*ob_stride + off) = v;
    }
}

// ---------------------------------------------------------------------------
// Flash attention: one CTA per (64-query tile, batch). 256 threads.
//   S[i,j] = sum_c qs[c,i]*ks[c,j]  (q pre-scaled by C^-0.5)
// f32x2 packed FMA throughout the two GEMMs:
//   QK^T: pairs over j (K pairs natural 64-bit from smem, q broadcast-packed)
//   PV:   pairs over channel (V pairs natural 64-bit, p broadcast-packed)
// Softmax state (m, l) lives in registers, replicated over the 16 lanes that
// share a row group; reductions via __shfl_xor (no smem, no extra barriers).
// ---------------------------------------------------------------------------
#define VSTRIDE 132

__global__ void __launch_bounds__(256, 1)
attn_kernel(const float* __restrict__ qkv, float* __restrict__ og)
{
    extern __shared__ float sm[];
    float* qs   = sm;                  // 128*64 = 8192
    float* ks   = sm + 8192;           // 8192
    float* vst  = sm + 16384;          // 64*132 = 8448
    float* st   = vst + 64*VSTRIDE;    // 64*64  = 4096

    int b  = blockIdx.y;
    int i0 = blockIdx.x * 64;
    const float* q = qkv + (long)b*3*CN;
    const float* k = q + CN;
    const float* v = q + 2*CN;
    int tid = threadIdx.x;
    int ti = tid >> 4, tj = tid & 15;
    const float scale = 0.08838834764831845f;  // 128^-0.5

    for (int idx = tid; idx < 8192; idx += 256) {
        int c = idx >> 6, ii = idx & 63;
        qs[idx] = q[(long)c*HWN + i0 + ii] * scale;
    }

    float m_r[4], l_r[4];
    #pragma unroll
    for (int r = 0; r < 4; ++r) { m_r[r] = -1e30f; l_r[r] = 0.f; }
    unsigned long long acc[4][4];      // [row][ch-pair] : O accum, 2 ch per reg
    #pragma unroll
    for (int r = 0; r < 4; ++r)
        #pragma unroll
        for (int cc = 0; cc < 4; ++cc) acc[r][cc] = 0ULL;
    __syncthreads();

    for (int jt = 0; jt < 64; ++jt) {
        int j0 = jt * 64;
        // load K tile [c][j] and V tile transposed [j][c]
        #pragma unroll 8
        for (int idx = tid; idx < 8192; idx += 256) {
            int c = idx >> 6, jj = idx & 63;
            float kv = k[(long)c*HWN + j0 + jj];
            float vv = v[(long)c*HWN + j0 + jj];
            ks[idx] = kv;
            vst[jj*VSTRIDE + c] = vv;
        }
        __syncthreads();

        // ---- S = Q^T K : 4 rows x (2 j-pairs) of f32x2 accumulators ----
        unsigned long long s2[4][2];
        #pragma unroll
        for (int r = 0; r < 4; ++r) { s2[r][0] = 0ULL; s2[r][1] = 0ULL; }
        const float* qp = qs + ti*4;
        const float* kp = ks + tj*4;
        #pragma unroll 4
        for (int c = 0; c < CHN; ++c) {
            float4 q4 = *(const float4*)(qp + c*64);
            ulonglong2 k2 = *(const ulonglong2*)(kp + c*64);   // (k0,k1),(k2,k3)
            unsigned long long q0 = pk2(q4.x), q1 = pk2(q4.y);
            unsigned long long q2 = pk2(q4.z), q3 = pk2(q4.w);
            s2[0][0] = ffma2(q0, k2.x, s2[0][0]); s2[0][1] = ffma2(q0, k2.y, s2[0][1]);
            s2[1][0] = ffma2(q1, k2.x, s2[1][0]); s2[1][1] = ffma2(q1, k2.y, s2[1][1]);
            s2[2][0] = ffma2(q2, k2.x, s2[2][0]); s2[2][1] = ffma2(q2, k2.y, s2[2][1]);
            s2[3][0] = ffma2(q3, k2.x, s2[3][0]); s2[3][1] = ffma2(q3, k2.y, s2[3][1]);
        }

        // ---- softmax (register state; shfl reductions over 16-lane groups) ----
        float p[4][4];
        #pragma unroll
        for (int r = 0; r < 4; ++r) {
            unpk2(s2[r][0], p[r][0], p[r][1]);
            unpk2(s2[r][1], p[r][2], p[r][3]);
        }
        float mn[4], co[4];
        #pragma unroll
        for (int r = 0; r < 4; ++r) {
            float tm = fmaxf(fmaxf(p[r][0], p[r][1]), fmaxf(p[r][2], p[r][3]));
            #pragma unroll
            for (int sft = 1; sft < 16; sft <<= 1)
                tm = fmaxf(tm, __shfl_xor_sync(0xffffffffu, tm, sft));
            mn[r] = fmaxf(m_r[r], tm);
            co[r] = __expf(m_r[r] - mn[r]);
            m_r[r] = mn[r];
        }
        #pragma unroll
        for (int r = 0; r < 4; ++r) {
            float rsum = 0.f;
            #pragma unroll
            for (int j = 0; j < 4; ++j) {
                p[r][j] = __expf(p[r][j] - mn[r]);
                rsum += p[r][j];
            }
            #pragma unroll
            for (int sft = 1; sft < 16; sft <<= 1)
                rsum += __shfl_xor_sync(0xffffffffu, rsum, sft);
            l_r[r] = l_r[r]*co[r] + rsum;
            *(float4*)(st + (ti*4 + r)*64 + tj*4) =
                make_float4(p[r][0], p[r][1], p[r][2], p[r][3]);
            unsigned long long co2 = pk2(co[r]);
            #pragma unroll
            for (int cc = 0; cc < 4; ++cc) acc[r][cc] = fmul2(co2, acc[r][cc]);
        }
        __syncthreads();

        // ---- O += P V^T : V channel-pairs natural, p broadcast-packed ----
        const float* vp = vst + tj*8;
        const float* sp = st + (ti*4)*64;
        #pragma unroll 4
        for (int j = 0; j < 64; ++j) {
            ulonglong2 va = *(const ulonglong2*)(vp + j*VSTRIDE);       // ch 0-3
            ulonglong2 vb = *(const ulonglong2*)(vp + j*VSTRIDE + 4);   // ch 4-7
            unsigned long long p0 = pk2(sp[0*64 + j]);
            unsigned long long p1 = pk2(sp[1*64 + j]);
            unsigned long long p2 = pk2(sp[2*64 + j]);
            unsigned long long p3 = pk2(sp[3*64 + j]);
            acc[0][0] = ffma2(p0, va.x, acc[0][0]); acc[0][1] = ffma2(p0, va.y, acc[0][1]);
            acc[0][2] = ffma2(p0, vb.x, acc[0][2]); acc[0][3] = ffma2(p0, vb.y, acc[0][3]);
            acc[1][0] = ffma2(p1, va.x, acc[1][0]); acc[1][1] = ffma2(p1, va.y, acc[1][1]);
            acc[1][2] = ffma2(p1, vb.x, acc[1][2]); acc[1][3] = ffma2(p1, vb.y, acc[1][3]);
            acc[2][0] = ffma2(p2, va.x, acc[2][0]); acc[2][1] = ffma2(p2, va.y, acc[2][1]);
            acc[2][2] = ffma2(p2, vb.x, acc[2][2]); acc[2][3] = ffma2(p2, vb.y, acc[2][3]);
            acc[3][0] = ffma2(p3, va.x, acc[3][0]); acc[3][1] = ffma2(p3, va.y, acc[3][1]);
            acc[3][2] = ffma2(p3, vb.x, acc[3][2]); acc[3][3] = ffma2(p3, vb.y, acc[3][3]);
        }
        __syncthreads();
    }

    // ---- epilogue: O / l, stage to [c][ii] layout for coalesced store ----
    float linv[4];
    #pragma unroll
    for (int r = 0; r < 4; ++r) linv[r] = 1.0f / l_r[r];
    #pragma unroll
    for (int r = 0; r < 4; ++r) {
        #pragma unroll
        for (int cc = 0; cc < 4; ++cc) {
            float a, bq;
            unpk2(acc[r][cc], a, bq);
            qs[(tj*8 + 2*cc + 0)*64 + ti*4 + r] = a  * linv[r];
            qs[(tj*8 + 2*cc + 1)*64 + ti*4 + r] = bq * linv[r];
        }
    }
    __syncthreads();

    float* ob = og + (long)b*CN;
    for (int idx = tid; idx < 8192; idx += 256) {
        int c = idx >> 6, ii = idx & 63;
        ob[(long)c*HWN + i0 + ii] = qs[idx];
    }
}

// ---------------------------------------------------------------------------
extern "C" void kernel_launch(void* const* d_in, const int* in_sizes, int n_in,
                              void* d_out, int out_size)
{
    const float* x      = (const float*)d_in[0];
    const float* gn_w   = (const float*)d_in[1];
    const float* gn_b   = (const float*)d_in[2];
    const float* qkv_w  = (const float*)d_in[3];
    const float* qkv_b  = (const float*)d_in[4];
    const float* proj_w = (const float*)d_in[5];
    const float* proj_b = (const float*)d_in[6];
    float* out = (float*)d_out;

    float *H, *QKV, *O;
    cudaGetSymbolAddress((void**)&H,   g_H);
    cudaGetSymbolAddress((void**)&QKV, g_QKV);
    cudaGetSymbolAddress((void**)&O,   g_O);

    const int CONV_SMEM = 2 * 8192 * 4;                         // 64 KB
    const int ATTN_SMEM = (8192 + 8192 + 64*VSTRIDE + 4096)*4;  // ~113 KB
    cudaFuncSetAttribute(conv1x1_kernel, cudaFuncAttributeMaxDynamicSharedMemorySize, CONV_SMEM);
    cudaFuncSetAttribute(attn_kernel,    cudaFuncAttributeMaxDynamicSharedMemorySize, ATTN_SMEM);

    // 1) GroupNorm
    gn_kernel<<<BATCH*GRP, 256>>>(x, gn_w, gn_b, H);
    // 2) QKV 1x1 conv: [384,128] @ [128,4096] per batch
    conv1x1_kernel<<<dim3(64, 6, BATCH), 256, CONV_SMEM>>>(H, qkv_w, qkv_b, QKV, 3L*CN, nullptr);
    // 3) Flash attention (f32x2 packed)
    attn_kernel<<<dim3(64, BATCH), 256, ATTN_SMEM>>>(QKV, O);
    // 4) proj 1x1 conv + residual -> d_out
    conv1x1_kernel<<<dim3(64, 2, BATCH), 256, CONV_SMEM>>>(O, proj_w, proj_b, out, (long)CN, x);
}